// round 6
// baseline (speedup 1.0000x reference)
#include <cuda_runtime.h>
#include <cuda_bf16.h>

// ---------------- problem constants (fixed by the dataset) ----------------
#define MAXN 100000
#define MAXE 1600000
#define HID 64

// ---------------- device scratch (no allocation allowed) ------------------
__device__ float d_bufA[MAXN * HID];
__device__ float d_bufB[MAXN * HID];
__device__ float d_dis[MAXN];          // deg^{-1/2}
__device__ int   d_cnt[MAXN];          // in-degree (without self loop)
__device__ int   d_off[MAXN + 1];      // CSR offsets
__device__ int   d_cursor[MAXN];       // fill cursors
__device__ int   d_csrc[MAXE];         // CSR: src node per incoming edge slot
__device__ int   d_partials[128];      // scan block partials
__device__ float d_pooled[64 * HID];   // per-graph means
__device__ int   g_is64;               // 1 if index tensors are int64

// ---------------- packed fp32x2 helpers (Blackwell) ------------------------
__device__ __forceinline__ float2 ffma2(float2 a, float2 b, float2 c) {
    float2 d;
    asm("fma.rn.f32x2 %0, %1, %2, %3;"
        : "=l"(reinterpret_cast<unsigned long long&>(d))
        : "l"(reinterpret_cast<unsigned long long&>(a)),
          "l"(reinterpret_cast<unsigned long long&>(b)),
          "l"(reinterpret_cast<unsigned long long&>(c)));
    return d;
}
__device__ __forceinline__ float2 fadd2(float2 a, float2 b) {
    float2 d;
    asm("add.rn.f32x2 %0, %1, %2;"
        : "=l"(reinterpret_cast<unsigned long long&>(d))
        : "l"(reinterpret_cast<unsigned long long&>(a)),
          "l"(reinterpret_cast<unsigned long long&>(b)));
    return d;
}
__device__ __forceinline__ float4 fadd4(float4 a, float4 b) {
    float2 lo = fadd2(make_float2(a.x, a.y), make_float2(b.x, b.y));
    float2 hi = fadd2(make_float2(a.z, a.w), make_float2(b.z, b.w));
    return make_float4(lo.x, lo.y, hi.x, hi.y);
}

// ---------------- index dtype detection -----------------------------------
__global__ void k_detect(const void* __restrict__ ei) {
    const long long* p = (const long long*)ei;
    int ok = 1;
#pragma unroll
    for (int i = 0; i < 16; i++) {
        long long v = p[i];
        if (v < 0 || v >= MAXN) ok = 0;
    }
    g_is64 = ok;
}

__device__ __forceinline__ int load_idx(const void* p, long long i) {
    return g_is64 ? (int)((const long long*)p)[i] : ((const int*)p)[i];
}
__device__ __forceinline__ long long load_batch(const void* p, int i) {
    return g_is64 ? ((const long long*)p)[i] : (long long)((const int*)p)[i];
}

// ---------------- CSR build ----------------

__global__ void k_zero_cnt(int N) {
    int i = blockIdx.x * blockDim.x + threadIdx.x;
    if (i < N) d_cnt[i] = 0;
}

__global__ void k_count(const void* __restrict__ ei, int E) {
    int e = blockIdx.x * blockDim.x + threadIdx.x;
    if (e < E) {
        int dst = load_idx(ei, (long long)E + e);
        atomicAdd(&d_cnt[dst], 1);
    }
}

// per-1024 block sums + dis = rsqrt(deg+1)
__global__ void k_blocksum(int N) {
    __shared__ int sh[256];
    int b = blockIdx.x, t = threadIdx.x;
    int base = b * 1024;
    int s = 0;
#pragma unroll
    for (int i = 0; i < 4; i++) {
        int idx = base + t + i * 256;
        if (idx < N) {
            int c = d_cnt[idx];
            s += c;
            d_dis[idx] = rsqrtf((float)(c + 1));
        }
    }
    sh[t] = s;
    __syncthreads();
    for (int o = 128; o > 0; o >>= 1) {
        if (t < o) sh[t] += sh[t + o];
        __syncthreads();
    }
    if (t == 0) d_partials[b] = sh[0];
}

__global__ void k_scanpart(int nb, int N, int E) {
    __shared__ int sh[128];
    int t = threadIdx.x;
    sh[t] = (t < nb) ? d_partials[t] : 0;
    __syncthreads();
    for (int o = 1; o < 128; o <<= 1) {
        int v = (t >= o) ? sh[t - o] : 0;
        __syncthreads();
        sh[t] += v;
        __syncthreads();
    }
    if (t < nb) d_partials[t] = (t == 0) ? 0 : sh[t - 1];
    if (t == 0) d_off[N] = E;
}

__global__ void k_scanblock(int N) {
    __shared__ int sh[1024];
    int b = blockIdx.x, t = threadIdx.x;
    int gid = b * 1024 + t;
    int v = (gid < N) ? d_cnt[gid] : 0;
    sh[t] = v;
    __syncthreads();
    for (int o = 1; o < 1024; o <<= 1) {
        int u = (t >= o) ? sh[t - o] : 0;
        __syncthreads();
        sh[t] += u;
        __syncthreads();
    }
    if (gid < N) {
        int excl = sh[t] - v + d_partials[b];
        d_off[gid] = excl;
        d_cursor[gid] = excl;
    }
}

__global__ void k_fill(const void* __restrict__ ei, int E) {
    int e = blockIdx.x * blockDim.x + threadIdx.x;
    if (e < E) {
        int dst = load_idx(ei, (long long)E + e);
        int src = load_idx(ei, e);
        int p = atomicAdd(&d_cursor[dst], 1);
        d_csrc[p] = src;
    }
}

// ---------------- GEMM: C[row] = dis[row] * (A[row] @ B), B is K x 64 ------
// BM=128, BN=64, BK=16; 256 threads; 8 rows x 4 cols per thread (f32x2).
__global__ __launch_bounds__(256) void k_gemm(const float* __restrict__ Aext,
                                              const int src, const int dst,
                                              const float* __restrict__ B,
                                              int N, int K) {
    const float* A = (src == 0) ? Aext : (src == 1 ? d_bufA : d_bufB);
    float* C = (dst == 1) ? d_bufA : d_bufB;

    __shared__ float As[16][128];
    __shared__ float Bs[16][64];
    int block_row = blockIdx.x * 128;
    int t = threadIdx.x;
    int tx = t & 15;          // col group: cols tx*4 .. tx*4+3
    int ty = t >> 4;          // row group: rows ty*8 .. ty*8+7

    float2 acc[4][4];         // [c][row_pair]
#pragma unroll
    for (int c = 0; c < 4; c++)
#pragma unroll
        for (int rp = 0; rp < 4; rp++) acc[c][rp] = make_float2(0.f, 0.f);

    for (int k0 = 0; k0 < K; k0 += 16) {
        {
            int m = t >> 1;            // 0..127
            int kk = (t & 1) * 8;      // 0 or 8
            int row = block_row + m;
            float4 v0 = make_float4(0.f, 0.f, 0.f, 0.f);
            float4 v1 = make_float4(0.f, 0.f, 0.f, 0.f);
            if (row < N) {
                v0 = *(const float4*)&A[(long long)row * K + k0 + kk];
                v1 = *(const float4*)&A[(long long)row * K + k0 + kk + 4];
            }
            As[kk + 0][m] = v0.x; As[kk + 1][m] = v0.y;
            As[kk + 2][m] = v0.z; As[kk + 3][m] = v0.w;
            As[kk + 4][m] = v1.x; As[kk + 5][m] = v1.y;
            As[kk + 6][m] = v1.z; As[kk + 7][m] = v1.w;
        }
        {
            int kk = t >> 4;           // 0..15
            int n = (t & 15) * 4;
            *(float4*)&Bs[kk][n] = *(const float4*)&B[(k0 + kk) * 64 + n];
        }
        __syncthreads();

#pragma unroll
        for (int kk = 0; kk < 16; kk++) {
            float4 alo = *(float4*)&As[kk][ty * 8];
            float4 ahi = *(float4*)&As[kk][ty * 8 + 4];
            float2 a2[4] = {{alo.x, alo.y}, {alo.z, alo.w},
                            {ahi.x, ahi.y}, {ahi.z, ahi.w}};
            float4 b4 = *(float4*)&Bs[kk][tx * 4];
            float bb[4] = {b4.x, b4.y, b4.z, b4.w};
#pragma unroll
            for (int c = 0; c < 4; c++) {
                float2 bc = make_float2(bb[c], bb[c]);
#pragma unroll
                for (int rp = 0; rp < 4; rp++)
                    acc[c][rp] = ffma2(a2[rp], bc, acc[c][rp]);
            }
        }
        __syncthreads();
    }

    // epilogue: prescale by dis[row], write h' = dis * (A@W)
#pragma unroll
    for (int r = 0; r < 8; r++) {
        int row = block_row + ty * 8 + r;
        if (row < N) {
            float s = d_dis[row];
            int rp = r >> 1;
            float4 o;
            if (r & 1) {
                o.x = s * acc[0][rp].y; o.y = s * acc[1][rp].y;
                o.z = s * acc[2][rp].y; o.w = s * acc[3][rp].y;
            } else {
                o.x = s * acc[0][rp].x; o.y = s * acc[1][rp].x;
                o.z = s * acc[2][rp].x; o.w = s * acc[3][rp].x;
            }
            *(float4*)&C[(long long)row * 64 + tx * 4] = o;
        }
    }
}

// ---------------- aggregation --------------------------------------------
// h' = dis * (A@W) prescaled by GEMM epilogue.
// out[i] = dis[i] * (h'[i] + sum_{j in N(i)} h'[j]) + bias   (+ relu)
// One warp per node; lanes 0-15 process even edge slots, lanes 16-31 odd
// slots; each lane loads a float4 (16B) of the 256B feature row -> 1 gather
// LDG.128 + 1 index LDG per edge PAIR. Final shfl_xor(16) combines halves.
__global__ __launch_bounds__(256) void k_agg(const int src, const int dst,
                                             const float* __restrict__ bias,
                                             int N, const int do_relu) {
    const float* hin = (src == 1) ? d_bufA : d_bufB;
    float* hout = (dst == 1) ? d_bufA : d_bufB;

    int node = blockIdx.x * 8 + (threadIdx.x >> 5);
    if (node >= N) return;
    int lane = threadIdx.x & 31;
    int half = lane >> 4;         // 0: even slots, 1: odd slots
    int fc = (lane & 15) * 4;     // feature chunk base

    float4 acc = make_float4(0.f, 0.f, 0.f, 0.f);
    int j = __ldg(&d_off[node]);
    int jend = __ldg(&d_off[node + 1]);

    // 4 pairs (8 edges) per iteration
    for (; j + 8 <= jend; j += 8) {
        int sA = __ldg(&d_csrc[j + 0 + half]);
        int sB = __ldg(&d_csrc[j + 2 + half]);
        int sC = __ldg(&d_csrc[j + 4 + half]);
        int sD = __ldg(&d_csrc[j + 6 + half]);
        float4 vA = __ldg((const float4*)&hin[(long long)sA * 64 + fc]);
        float4 vB = __ldg((const float4*)&hin[(long long)sB * 64 + fc]);
        float4 vC = __ldg((const float4*)&hin[(long long)sC * 64 + fc]);
        float4 vD = __ldg((const float4*)&hin[(long long)sD * 64 + fc]);
        float4 t0 = fadd4(vA, vB);
        float4 t1 = fadd4(vC, vD);
        acc = fadd4(acc, fadd4(t0, t1));
    }
    // remaining pairs
    for (; j + 2 <= jend; j += 2) {
        int s = __ldg(&d_csrc[j + half]);
        float4 v = __ldg((const float4*)&hin[(long long)s * 64 + fc]);
        acc = fadd4(acc, v);
    }
    // odd tail edge: low half only
    if (j < jend && half == 0) {
        int s = __ldg(&d_csrc[j]);
        float4 v = __ldg((const float4*)&hin[(long long)s * 64 + fc]);
        acc = fadd4(acc, v);
    }

    // combine even/odd halves
    acc.x += __shfl_xor_sync(0xffffffffu, acc.x, 16);
    acc.y += __shfl_xor_sync(0xffffffffu, acc.y, 16);
    acc.z += __shfl_xor_sync(0xffffffffu, acc.z, 16);
    acc.w += __shfl_xor_sync(0xffffffffu, acc.w, 16);

    if (half == 0) {
        float4 self = __ldg((const float4*)&hin[(long long)node * 64 + fc]);
        float di = d_dis[node];
        float4 b = __ldg((const float4*)&bias[fc]);
        float4 o;
        o.x = fmaf(di, acc.x + self.x, b.x);
        o.y = fmaf(di, acc.y + self.y, b.y);
        o.z = fmaf(di, acc.z + self.z, b.z);
        o.w = fmaf(di, acc.w + self.w, b.w);
        if (do_relu) {
            o.x = fmaxf(o.x, 0.f);
            o.y = fmaxf(o.y, 0.f);
            o.z = fmaxf(o.z, 0.f);
            o.w = fmaxf(o.w, 0.f);
        }
        *(float4*)&hout[(long long)node * 64 + fc] = o;
    }
}

// ---------------- global mean pool (batch is sorted -> binary search) -----
__device__ __forceinline__ int lower_bound_b(const void* b, int N, long long v) {
    int lo = 0, hi = N;
    while (lo < hi) {
        int m = (lo + hi) >> 1;
        if (load_batch(b, m) < v) lo = m + 1; else hi = m;
    }
    return lo;
}

// reads final features from d_bufB
__global__ void k_pool(const void* __restrict__ batch, int N) {
    int g = blockIdx.x;
    int start = lower_bound_b(batch, N, (long long)g);
    int end = lower_bound_b(batch, N, (long long)g + 1);
    int f = threadIdx.x & 63;
    int r = threadIdx.x >> 6;   // 0..3
    float acc = 0.f;
    for (int i = start + r; i < end; i += 4)
        acc += d_bufB[(long long)i * 64 + f];
    __shared__ float sh[4][64];
    sh[r][f] = acc;
    __syncthreads();
    if (r == 0) {
        float v = sh[0][f] + sh[1][f] + sh[2][f] + sh[3][f];
        float cnt = (float)(end - start);
        d_pooled[g * 64 + f] = v / fmaxf(cnt, 1.0f);
    }
}

// ---------------- classifier MLP ------------------------------------------
__global__ void k_cls(const float* __restrict__ Wc1, const float* __restrict__ bc1,
                      const float* __restrict__ Wc2, const float* __restrict__ bc2,
                      float* __restrict__ out, int G) {
    int g = threadIdx.x;
    if (g >= G) return;
    float p[64];
#pragma unroll
    for (int k = 0; k < 64; k++) p[k] = d_pooled[g * 64 + k];
    float o0 = bc2[0], o1 = bc2[1];
#pragma unroll
    for (int jj = 0; jj < 32; jj++) {
        float h = bc1[jj];
#pragma unroll
        for (int k = 0; k < 64; k++) h = fmaf(p[k], Wc1[k * 32 + jj], h);
        h = fmaxf(h, 0.f);
        o0 = fmaf(h, Wc2[jj * 2 + 0], o0);
        o1 = fmaf(h, Wc2[jj * 2 + 1], o1);
    }
    out[g * 2 + 0] = o0;
    out[g * 2 + 1] = o1;
}

// ---------------- launch ---------------------------------------------------
extern "C" void kernel_launch(void* const* d_in, const int* in_sizes, int n_in,
                              void* d_out, int out_size) {
    const float* x     = (const float*)d_in[0];
    const void*  ei    = d_in[1];
    const void*  batch = d_in[2];
    const float* W1 = (const float*)d_in[3];
    const float* b1 = (const float*)d_in[4];
    const float* W2 = (const float*)d_in[5];
    const float* b2 = (const float*)d_in[6];
    const float* W3 = (const float*)d_in[7];
    const float* b3 = (const float*)d_in[8];
    const float* Wc1 = (const float*)d_in[9];
    const float* bc1 = (const float*)d_in[10];
    const float* Wc2 = (const float*)d_in[11];
    const float* bc2 = (const float*)d_in[12];
    float* out = (float*)d_out;

    int N = in_sizes[0] / 128;
    int E = in_sizes[1] / 2;
    int G = out_size / 2;

    int nb = (N + 1023) / 1024;

    // dtype detection + CSR build (computes d_dis before GEMMs)
    k_detect<<<1, 1>>>(ei);
    k_zero_cnt<<<(N + 255) / 256, 256>>>(N);
    k_count<<<(E + 255) / 256, 256>>>(ei, E);
    k_blocksum<<<nb, 256>>>(N);
    k_scanpart<<<1, 128>>>(nb, N, E);
    k_scanblock<<<nb, 1024>>>(N);
    k_fill<<<(E + 255) / 256, 256>>>(ei, E);

    int gemm_blocks = (N + 127) / 128;
    int agg_blocks = (N + 7) / 8;

    // conv1: h' = dis*(x @ W1) -> bufA; agg bufA -> bufB (relu)
    k_gemm<<<gemm_blocks, 256>>>(x, 0, 1, W1, N, 128);
    k_agg<<<agg_blocks, 256>>>(1, 2, b1, N, 1);
    // conv2
    k_gemm<<<gemm_blocks, 256>>>(nullptr, 2, 1, W2, N, 64);
    k_agg<<<agg_blocks, 256>>>(1, 2, b2, N, 1);
    // conv3 (no relu)
    k_gemm<<<gemm_blocks, 256>>>(nullptr, 2, 1, W3, N, 64);
    k_agg<<<agg_blocks, 256>>>(1, 2, b3, N, 0);

    // pool + classifier
    k_pool<<<G, 256>>>(batch, N);
    k_cls<<<1, 64>>>(Wc1, bc1, Wc2, bc2, out, G);
}

// round 7
// speedup vs baseline: 1.1047x; 1.1047x over previous
#include <cuda_runtime.h>
#include <cuda_fp16.h>

// ---------------- problem constants (fixed by the dataset) ----------------
#define MAXN 100000
#define MAXE 1600000
#define HID 64

// ---------------- device scratch (no allocation allowed) ------------------
__device__ __half d_h[MAXN * HID];     // h' = dis*(A@W)  (gather source)
__device__ __half d_g[MAXN * HID];     // agg output / next GEMM input
__device__ float d_dis[MAXN];          // deg^{-1/2}
__device__ int   d_cnt[MAXN];          // in-degree (without self loop)
__device__ int   d_off[MAXN + 1];      // CSR offsets
__device__ int   d_cursor[MAXN];       // fill cursors
__device__ int   d_csrc[MAXE];         // CSR: src node per incoming edge slot
__device__ int   d_partials[128];      // scan block partials
__device__ float d_pooled[64 * HID];   // per-graph means
__device__ int   g_is64;               // 1 if index tensors are int64

// ---------------- packed fp32x2 helpers (Blackwell) ------------------------
__device__ __forceinline__ float2 ffma2(float2 a, float2 b, float2 c) {
    float2 d;
    asm("fma.rn.f32x2 %0, %1, %2, %3;"
        : "=l"(reinterpret_cast<unsigned long long&>(d))
        : "l"(reinterpret_cast<unsigned long long&>(a)),
          "l"(reinterpret_cast<unsigned long long&>(b)),
          "l"(reinterpret_cast<unsigned long long&>(c)));
    return d;
}
__device__ __forceinline__ float2 fadd2(float2 a, float2 b) {
    float2 d;
    asm("add.rn.f32x2 %0, %1, %2;"
        : "=l"(reinterpret_cast<unsigned long long&>(d))
        : "l"(reinterpret_cast<unsigned long long&>(a)),
          "l"(reinterpret_cast<unsigned long long&>(b)));
    return d;
}
__device__ __forceinline__ float4 fadd4(float4 a, float4 b) {
    float2 lo = fadd2(make_float2(a.x, a.y), make_float2(b.x, b.y));
    float2 hi = fadd2(make_float2(a.z, a.w), make_float2(b.z, b.w));
    return make_float4(lo.x, lo.y, hi.x, hi.y);
}

// ---------------- index helpers -------------------------------------------
__device__ __forceinline__ int load_idx(const void* p, long long i) {
    return g_is64 ? (int)((const long long*)p)[i] : ((const int*)p)[i];
}
__device__ __forceinline__ long long load_batch(const void* p, int i) {
    return g_is64 ? ((const long long*)p)[i] : (long long)((const int*)p)[i];
}

// ---------------- CSR build ------------------------------------------------
// zero counts + (block 0 thread 0) detect index dtype
__global__ void k_zero_cnt(const void* __restrict__ ei, int N) {
    int i = blockIdx.x * blockDim.x + threadIdx.x;
    if (i < N) d_cnt[i] = 0;
    if (blockIdx.x == 0 && threadIdx.x == 0) {
        const long long* p = (const long long*)ei;
        int ok = 1;
#pragma unroll
        for (int k = 0; k < 16; k++) {
            long long v = p[k];
            if (v < 0 || v >= MAXN) ok = 0;
        }
        g_is64 = ok;
    }
}

__global__ void k_count(const void* __restrict__ ei, int E) {
    int e = blockIdx.x * blockDim.x + threadIdx.x;
    if (e < E) {
        int dst = load_idx(ei, (long long)E + e);
        atomicAdd(&d_cnt[dst], 1);
    }
}

// per-1024 block sums + dis = rsqrt(deg+1)
__global__ void k_blocksum(int N) {
    __shared__ int sh[256];
    int b = blockIdx.x, t = threadIdx.x;
    int base = b * 1024;
    int s = 0;
#pragma unroll
    for (int i = 0; i < 4; i++) {
        int idx = base + t + i * 256;
        if (idx < N) {
            int c = d_cnt[idx];
            s += c;
            d_dis[idx] = rsqrtf((float)(c + 1));
        }
    }
    sh[t] = s;
    __syncthreads();
    for (int o = 128; o > 0; o >>= 1) {
        if (t < o) sh[t] += sh[t + o];
        __syncthreads();
    }
    if (t == 0) d_partials[b] = sh[0];
}

__global__ void k_scanpart(int nb, int N, int E) {
    __shared__ int sh[128];
    int t = threadIdx.x;
    sh[t] = (t < nb) ? d_partials[t] : 0;
    __syncthreads();
    for (int o = 1; o < 128; o <<= 1) {
        int v = (t >= o) ? sh[t - o] : 0;
        __syncthreads();
        sh[t] += v;
        __syncthreads();
    }
    if (t < nb) d_partials[t] = (t == 0) ? 0 : sh[t - 1];
    if (t == 0) d_off[N] = E;
}

__global__ void k_scanblock(int N) {
    __shared__ int sh[1024];
    int b = blockIdx.x, t = threadIdx.x;
    int gid = b * 1024 + t;
    int v = (gid < N) ? d_cnt[gid] : 0;
    sh[t] = v;
    __syncthreads();
    for (int o = 1; o < 1024; o <<= 1) {
        int u = (t >= o) ? sh[t - o] : 0;
        __syncthreads();
        sh[t] += u;
        __syncthreads();
    }
    if (gid < N) {
        int excl = sh[t] - v + d_partials[b];
        d_off[gid] = excl;
        d_cursor[gid] = excl;
    }
}

__global__ void k_fill(const void* __restrict__ ei, int E) {
    int e = blockIdx.x * blockDim.x + threadIdx.x;
    if (e < E) {
        int dst = load_idx(ei, (long long)E + e);
        int src = load_idx(ei, e);
        int p = atomicAdd(&d_cursor[dst], 1);
        d_csrc[p] = src;
    }
}

// ---------------- GEMM: d_h[row] = half( dis[row] * (A[row] @ B) ) ---------
// BM=128, BN=64, BK=16; 256 threads; 8 rows x 4 cols per thread (f32x2).
// half_in=0: A = Aext (fp32, stride K); half_in=1: A = d_g (half, stride 64)
__global__ __launch_bounds__(256) void k_gemm(const float* __restrict__ Aext,
                                              const int half_in,
                                              const float* __restrict__ B,
                                              int N, int K) {
    __shared__ float As[16][128];
    __shared__ float Bs[16][64];
    int block_row = blockIdx.x * 128;
    int t = threadIdx.x;
    int tx = t & 15;          // col group: cols tx*4 .. tx*4+3
    int ty = t >> 4;          // row group: rows ty*8 .. ty*8+7

    float2 acc[4][4];         // [c][row_pair]
#pragma unroll
    for (int c = 0; c < 4; c++)
#pragma unroll
        for (int rp = 0; rp < 4; rp++) acc[c][rp] = make_float2(0.f, 0.f);

    for (int k0 = 0; k0 < K; k0 += 16) {
        // A tile: 128 rows x 16 k (transposed into As[kk][m]); 8 vals/thread
        {
            int m = t >> 1;            // 0..127
            int kk = (t & 1) * 8;      // 0 or 8
            int row = block_row + m;
            if (half_in) {
                uint4 raw = make_uint4(0u, 0u, 0u, 0u);
                if (row < N)
                    raw = *(const uint4*)&d_g[(long long)row * 64 + k0 + kk];
                float2 f0 = __half22float2(*(__half2*)&raw.x);
                float2 f1 = __half22float2(*(__half2*)&raw.y);
                float2 f2 = __half22float2(*(__half2*)&raw.z);
                float2 f3 = __half22float2(*(__half2*)&raw.w);
                As[kk + 0][m] = f0.x; As[kk + 1][m] = f0.y;
                As[kk + 2][m] = f1.x; As[kk + 3][m] = f1.y;
                As[kk + 4][m] = f2.x; As[kk + 5][m] = f2.y;
                As[kk + 6][m] = f3.x; As[kk + 7][m] = f3.y;
            } else {
                float4 v0 = make_float4(0.f, 0.f, 0.f, 0.f);
                float4 v1 = make_float4(0.f, 0.f, 0.f, 0.f);
                if (row < N) {
                    v0 = *(const float4*)&Aext[(long long)row * K + k0 + kk];
                    v1 = *(const float4*)&Aext[(long long)row * K + k0 + kk + 4];
                }
                As[kk + 0][m] = v0.x; As[kk + 1][m] = v0.y;
                As[kk + 2][m] = v0.z; As[kk + 3][m] = v0.w;
                As[kk + 4][m] = v1.x; As[kk + 5][m] = v1.y;
                As[kk + 6][m] = v1.z; As[kk + 7][m] = v1.w;
            }
        }
        // B tile: 16 x 64
        {
            int kk = t >> 4;
            int n = (t & 15) * 4;
            *(float4*)&Bs[kk][n] = *(const float4*)&B[(k0 + kk) * 64 + n];
        }
        __syncthreads();

#pragma unroll
        for (int kk = 0; kk < 16; kk++) {
            float4 alo = *(float4*)&As[kk][ty * 8];
            float4 ahi = *(float4*)&As[kk][ty * 8 + 4];
            float2 a2[4] = {{alo.x, alo.y}, {alo.z, alo.w},
                            {ahi.x, ahi.y}, {ahi.z, ahi.w}};
            float4 b4 = *(float4*)&Bs[kk][tx * 4];
            float bb[4] = {b4.x, b4.y, b4.z, b4.w};
#pragma unroll
            for (int c = 0; c < 4; c++) {
                float2 bc = make_float2(bb[c], bb[c]);
#pragma unroll
                for (int rp = 0; rp < 4; rp++)
                    acc[c][rp] = ffma2(a2[rp], bc, acc[c][rp]);
            }
        }
        __syncthreads();
    }

    // epilogue: prescale by dis[row], store as half
#pragma unroll
    for (int r = 0; r < 8; r++) {
        int row = block_row + ty * 8 + r;
        if (row < N) {
            float s = d_dis[row];
            int rp = r >> 1;
            float4 o;
            if (r & 1) {
                o.x = s * acc[0][rp].y; o.y = s * acc[1][rp].y;
                o.z = s * acc[2][rp].y; o.w = s * acc[3][rp].y;
            } else {
                o.x = s * acc[0][rp].x; o.y = s * acc[1][rp].x;
                o.z = s * acc[2][rp].x; o.w = s * acc[3][rp].x;
            }
            __half2 p0 = __floats2half2_rn(o.x, o.y);
            __half2 p1 = __floats2half2_rn(o.z, o.w);
            uint2 st;
            st.x = *(unsigned*)&p0;
            st.y = *(unsigned*)&p1;
            *(uint2*)&d_h[(long long)row * 64 + tx * 4] = st;
        }
    }
}

// ---------------- aggregation ---------------------------------------------
// d_h holds h' = dis*(A@W) in half precision.
// d_g[i] = half( dis[i]*(h'[i] + sum_{j in N(i)} h'[j]) + bias )  (+relu)
// One warp per node; lanes 0-15 even edge slots, 16-31 odd; each lane loads
// 4 halves (8B) of the 128B feature row -> 1 gather LDG.64 + 1 idx LDG per
// edge pair per lane-half. fp32 accumulation; shfl_xor(16) combines.
__global__ __launch_bounds__(256) void k_agg(const float* __restrict__ bias,
                                             int N, const int do_relu) {
    int node = blockIdx.x * 8 + (threadIdx.x >> 5);
    if (node >= N) return;
    int lane = threadIdx.x & 31;
    int half = lane >> 4;         // 0: even slots, 1: odd slots
    int fc = (lane & 15) * 4;     // feature chunk base (4 halves)

    float4 acc = make_float4(0.f, 0.f, 0.f, 0.f);
    int j = __ldg(&d_off[node]);
    int jend = __ldg(&d_off[node + 1]);

    for (; j + 8 <= jend; j += 8) {
        int sA = __ldg(&d_csrc[j + 0 + half]);
        int sB = __ldg(&d_csrc[j + 2 + half]);
        int sC = __ldg(&d_csrc[j + 4 + half]);
        int sD = __ldg(&d_csrc[j + 6 + half]);
        uint2 rA = __ldg((const uint2*)&d_h[(long long)sA * 64 + fc]);
        uint2 rB = __ldg((const uint2*)&d_h[(long long)sB * 64 + fc]);
        uint2 rC = __ldg((const uint2*)&d_h[(long long)sC * 64 + fc]);
        uint2 rD = __ldg((const uint2*)&d_h[(long long)sD * 64 + fc]);
        float2 aL = __half22float2(*(__half2*)&rA.x);
        float2 aH = __half22float2(*(__half2*)&rA.y);
        float2 bL = __half22float2(*(__half2*)&rB.x);
        float2 bH = __half22float2(*(__half2*)&rB.y);
        float2 cL = __half22float2(*(__half2*)&rC.x);
        float2 cH = __half22float2(*(__half2*)&rC.y);
        float2 dL = __half22float2(*(__half2*)&rD.x);
        float2 dH = __half22float2(*(__half2*)&rD.y);
        float4 t0 = make_float4(aL.x + bL.x, aL.y + bL.y, aH.x + bH.x, aH.y + bH.y);
        float4 t1 = make_float4(cL.x + dL.x, cL.y + dL.y, cH.x + dH.x, cH.y + dH.y);
        acc = fadd4(acc, fadd4(t0, t1));
    }
    for (; j + 2 <= jend; j += 2) {
        int s = __ldg(&d_csrc[j + half]);
        uint2 r = __ldg((const uint2*)&d_h[(long long)s * 64 + fc]);
        float2 lo = __half22float2(*(__half2*)&r.x);
        float2 hi = __half22float2(*(__half2*)&r.y);
        acc = fadd4(acc, make_float4(lo.x, lo.y, hi.x, hi.y));
    }
    if (j < jend && half == 0) {
        int s = __ldg(&d_csrc[j]);
        uint2 r = __ldg((const uint2*)&d_h[(long long)s * 64 + fc]);
        float2 lo = __half22float2(*(__half2*)&r.x);
        float2 hi = __half22float2(*(__half2*)&r.y);
        acc = fadd4(acc, make_float4(lo.x, lo.y, hi.x, hi.y));
    }

    acc.x += __shfl_xor_sync(0xffffffffu, acc.x, 16);
    acc.y += __shfl_xor_sync(0xffffffffu, acc.y, 16);
    acc.z += __shfl_xor_sync(0xffffffffu, acc.z, 16);
    acc.w += __shfl_xor_sync(0xffffffffu, acc.w, 16);

    if (half == 0) {
        uint2 rs = __ldg((const uint2*)&d_h[(long long)node * 64 + fc]);
        float2 slo = __half22float2(*(__half2*)&rs.x);
        float2 shi = __half22float2(*(__half2*)&rs.y);
        float di = d_dis[node];
        float4 b = __ldg((const float4*)&bias[fc]);
        float4 o;
        o.x = fmaf(di, acc.x + slo.x, b.x);
        o.y = fmaf(di, acc.y + slo.y, b.y);
        o.z = fmaf(di, acc.z + shi.x, b.z);
        o.w = fmaf(di, acc.w + shi.y, b.w);
        if (do_relu) {
            o.x = fmaxf(o.x, 0.f);
            o.y = fmaxf(o.y, 0.f);
            o.z = fmaxf(o.z, 0.f);
            o.w = fmaxf(o.w, 0.f);
        }
        __half2 q0 = __floats2half2_rn(o.x, o.y);
        __half2 q1 = __floats2half2_rn(o.z, o.w);
        uint2 st;
        st.x = *(unsigned*)&q0;
        st.y = *(unsigned*)&q1;
        *(uint2*)&d_g[(long long)node * 64 + fc] = st;
    }
}

// ---------------- global mean pool (batch sorted -> binary search) --------
__device__ __forceinline__ int lower_bound_b(const void* b, int N, long long v) {
    int lo = 0, hi = N;
    while (lo < hi) {
        int m = (lo + hi) >> 1;
        if (load_batch(b, m) < v) lo = m + 1; else hi = m;
    }
    return lo;
}

// reads final features from d_g (half); 16 feature-chunks x 16 row-lanes
__global__ void k_pool(const void* __restrict__ batch, int N) {
    int g = blockIdx.x;
    int start = lower_bound_b(batch, N, (long long)g);
    int end = lower_bound_b(batch, N, (long long)g + 1);
    int fc = (threadIdx.x & 15) * 4;   // 4 halves
    int r = threadIdx.x >> 4;          // 0..15
    float4 acc = make_float4(0.f, 0.f, 0.f, 0.f);
    for (int i = start + r; i < end; i += 16) {
        uint2 raw = __ldg((const uint2*)&d_g[(long long)i * 64 + fc]);
        float2 lo = __half22float2(*(__half2*)&raw.x);
        float2 hi = __half22float2(*(__half2*)&raw.y);
        acc = fadd4(acc, make_float4(lo.x, lo.y, hi.x, hi.y));
    }
    __shared__ float4 sh[16][16];
    sh[r][threadIdx.x & 15] = acc;
    __syncthreads();
    if (r == 0) {
        float4 v = sh[0][threadIdx.x & 15];
#pragma unroll
        for (int k = 1; k < 16; k++) {
            float4 u = sh[k][threadIdx.x & 15];
            v.x += u.x; v.y += u.y; v.z += u.z; v.w += u.w;
        }
        float inv = 1.0f / fmaxf((float)(end - start), 1.0f);
        d_pooled[g * 64 + fc + 0] = v.x * inv;
        d_pooled[g * 64 + fc + 1] = v.y * inv;
        d_pooled[g * 64 + fc + 2] = v.z * inv;
        d_pooled[g * 64 + fc + 3] = v.w * inv;
    }
}

// ---------------- classifier MLP ------------------------------------------
__global__ void k_cls(const float* __restrict__ Wc1, const float* __restrict__ bc1,
                      const float* __restrict__ Wc2, const float* __restrict__ bc2,
                      float* __restrict__ out, int G) {
    int g = threadIdx.x;
    if (g >= G) return;
    float p[64];
#pragma unroll
    for (int k = 0; k < 64; k++) p[k] = d_pooled[g * 64 + k];
    float o0 = bc2[0], o1 = bc2[1];
#pragma unroll
    for (int jj = 0; jj < 32; jj++) {
        float h = bc1[jj];
#pragma unroll
        for (int k = 0; k < 64; k++) h = fmaf(p[k], Wc1[k * 32 + jj], h);
        h = fmaxf(h, 0.f);
        o0 = fmaf(h, Wc2[jj * 2 + 0], o0);
        o1 = fmaf(h, Wc2[jj * 2 + 1], o1);
    }
    out[g * 2 + 0] = o0;
    out[g * 2 + 1] = o1;
}

// ---------------- launch ---------------------------------------------------
extern "C" void kernel_launch(void* const* d_in, const int* in_sizes, int n_in,
                              void* d_out, int out_size) {
    const float* x     = (const float*)d_in[0];
    const void*  ei    = d_in[1];
    const void*  batch = d_in[2];
    const float* W1 = (const float*)d_in[3];
    const float* b1 = (const float*)d_in[4];
    const float* W2 = (const float*)d_in[5];
    const float* b2 = (const float*)d_in[6];
    const float* W3 = (const float*)d_in[7];
    const float* b3 = (const float*)d_in[8];
    const float* Wc1 = (const float*)d_in[9];
    const float* bc1 = (const float*)d_in[10];
    const float* Wc2 = (const float*)d_in[11];
    const float* bc2 = (const float*)d_in[12];
    float* out = (float*)d_out;

    int N = in_sizes[0] / 128;
    int E = in_sizes[1] / 2;
    int G = out_size / 2;

    int nb = (N + 1023) / 1024;

    // CSR build (also computes d_dis and detects index dtype)
    k_zero_cnt<<<(N + 255) / 256, 256>>>(ei, N);
    k_count<<<(E + 255) / 256, 256>>>(ei, E);
    k_blocksum<<<nb, 256>>>(N);
    k_scanpart<<<1, 128>>>(nb, N, E);
    k_scanblock<<<nb, 1024>>>(N);
    k_fill<<<(E + 255) / 256, 256>>>(ei, E);

    int gemm_blocks = (N + 127) / 128;
    int agg_blocks = (N + 7) / 8;

    // conv1: h' = dis*(x @ W1) -> d_h; agg d_h -> d_g (relu)
    k_gemm<<<gemm_blocks, 256>>>(x, 0, W1, N, 128);
    k_agg<<<agg_blocks, 256>>>(b1, N, 1);
    // conv2
    k_gemm<<<gemm_blocks, 256>>>(nullptr, 1, W2, N, 64);
    k_agg<<<agg_blocks, 256>>>(b2, N, 1);
    // conv3 (no relu)
    k_gemm<<<gemm_blocks, 256>>>(nullptr, 1, W3, N, 64);
    k_agg<<<agg_blocks, 256>>>(b3, N, 0);

    // pool + classifier
    k_pool<<<G, 256>>>(batch, N);
    k_cls<<<1, 64>>>(Wc1, bc1, Wc2, bc2, out, G);
}